// round 17
// baseline (speedup 1.0000x reference)
#include <cuda_runtime.h>
#include <cuda_fp16.h>

#define QLEN 512
#define MLEN 512
#define KLEN 1024
#define BSZ 8
#define DMODEL 1024
#define NHEAD 16
#define DHEAD 64
#define DINNER 4096

// ---------------- scratch (no allocations allowed) ----------------
__device__ float g_core[QLEN * BSZ * DMODEL];
__device__ float g_attnout[QLEN * BSZ * DMODEL];
__device__ float g_ff[QLEN * BSZ * DMODEL];

__device__ __half g_BDrh[BSZ * NHEAD * QLEN * KLEN];
__device__ __half g_headsh[KLEN * BSZ * 3 * DMODEL];
__device__ __half g_cath[KLEN * BSZ * DMODEL];
__device__ __half g_pemh[KLEN * DMODEL];
__device__ __half g_rkh[KLEN * DMODEL];
__device__ __half g_coreh[QLEN * BSZ * DMODEL];
__device__ __half g_avech[QLEN * BSZ * DMODEL];
__device__ __half g_h1h[QLEN * BSZ * DINNER];

__device__ __half g_qkvwh[4 * 3 * DMODEL * DMODEL];
__device__ __half g_rwh[4 * DMODEL * DMODEL];
__device__ __half g_owh[4 * DMODEL * DMODEL];
__device__ __half g_w1h[4 * DINNER * DMODEL];
__device__ __half g_w2h[4 * DMODEL * DINNER];

// ---------------- helpers ----------------
__device__ __forceinline__ unsigned f2h2(float a, float b) {
    __half2 h = __floats2half2_rn(a, b);
    return *(unsigned*)&h;
}

__device__ __forceinline__ void mma16(float* c, const unsigned* a,
                                      unsigned b0, unsigned b1) {
    asm volatile(
        "mma.sync.aligned.m16n8k16.row.col.f32.f16.f16.f32 "
        "{%0,%1,%2,%3}, {%4,%5,%6,%7}, {%8,%9}, {%0,%1,%2,%3};"
        : "+f"(c[0]), "+f"(c[1]), "+f"(c[2]), "+f"(c[3])
        : "r"(a[0]), "r"(a[1]), "r"(a[2]), "r"(a[3]), "r"(b0), "r"(b1));
}

__device__ __forceinline__ void ldsm4(unsigned* r, const __half* p) {
    unsigned addr = (unsigned)__cvta_generic_to_shared(p);
    asm volatile("ldmatrix.sync.aligned.m8n8.x4.shared.b16 {%0,%1,%2,%3}, [%4];"
                 : "=r"(r[0]), "=r"(r[1]), "=r"(r[2]), "=r"(r[3])
                 : "r"(addr));
}

__device__ __forceinline__ void ldsm4t(unsigned* r, const __half* p) {
    unsigned addr = (unsigned)__cvta_generic_to_shared(p);
    asm volatile("ldmatrix.sync.aligned.m8n8.x4.trans.shared.b16 {%0,%1,%2,%3}, [%4];"
                 : "=r"(r[0]), "=r"(r[1]), "=r"(r[2]), "=r"(r[3])
                 : "r"(addr));
}

__device__ __forceinline__ void cpa16(const __half* smem_dst, const __half* gsrc) {
    unsigned d = (unsigned)__cvta_generic_to_shared(smem_dst);
    asm volatile("cp.async.cg.shared.global [%0], [%1], 16;" :: "r"(d), "l"(gsrc));
}
__device__ __forceinline__ void cp_commit() {
    asm volatile("cp.async.commit_group;");
}
__device__ __forceinline__ void cp_wait1() {
    asm volatile("cp.async.wait_group 1;");
}

// ---------------- weight fp32 -> fp16 ----------------
__global__ void w2h_kernel(const float* __restrict__ src, __half* __restrict__ dst,
                           int n4) {
    int i = blockIdx.x * 256 + threadIdx.x;
    if (i < n4) {
        float4 v = ((const float4*)src)[i];
        uint2 o = make_uint2(f2h2(v.x, v.y), f2h2(v.z, v.w));
        *(uint2*)(dst + (size_t)i * 4) = o;
    }
}

// ---------------- embedding lookup: core = emb[inp] * sqrt(D) ----------------
__global__ void embed_kernel(const int* __restrict__ inp,
                             const float* __restrict__ emb,
                             float* __restrict__ core) {
    int row = blockIdx.x;
    int tok = inp[row];
    const float4* src = (const float4*)(emb + (size_t)tok * DMODEL);
    float4* dst = (float4*)(core + (size_t)row * DMODEL);
    float4 v = src[threadIdx.x];
    v.x *= 32.f; v.y *= 32.f; v.z *= 32.f; v.w *= 32.f;
    dst[threadIdx.x] = v;
}

// ---------------- cat (fp16) = [mems_l ; core] ----------------
__global__ void cat_f16_kernel(const float* __restrict__ mems_l,
                               const float* __restrict__ core,
                               __half* __restrict__ cath) {
    int row = blockIdx.x;
    int t = threadIdx.x;
    const float* s = (row < MLEN * BSZ) ? mems_l + (size_t)row * DMODEL
                                        : core + (size_t)(row - MLEN * BSZ) * DMODEL;
    float4 v = ((const float4*)s)[t];
    uint2 o = make_uint2(f2h2(v.x, v.y), f2h2(v.z, v.w));
    *(uint2*)(cath + (size_t)row * DMODEL + t * 4) = o;
}

// ---------------- sinusoidal positional embedding (fp16) ----------------
__global__ void posemb_kernel(__half* __restrict__ pe) {
    int k = blockIdx.x;
    int j = threadIdx.x;
    double invf = exp(-(2.0 * (double)j / 1024.0) * log(10000.0));
    double ang = (double)(KLEN - 1 - k) * invf;
    pe[(size_t)k * DMODEL + j] = __float2half((float)sin(ang));
    pe[(size_t)k * DMODEL + 512 + j] = __float2half((float)cos(ang));
}

// ---------------- NT GEMM: fp16 A/B in gmem, cp.async 2-stage + ldmatrix -----
// C[M,N] = A[M,K] B[N,K]^T. CTA 128x128, k-tile 32.
// Row stride 40 halfs = 80B = 5*16B: every 16B cp.async dst is 16B-aligned.
template <bool RELU, bool HASBIAS, bool OUTF16>
__global__ __launch_bounds__(256, 2) void gemm_nt_h(
    const __half* __restrict__ A, const __half* __restrict__ B,
    const float* __restrict__ bias, float* __restrict__ C,
    __half* __restrict__ Ch, int M, int N, int K) {
    __shared__ __align__(16) __half sA[2][128 * 40];
    __shared__ __align__(16) __half sB[2][128 * 40];
    const int t = threadIdx.x;
    const int m0 = blockIdx.y * 128, n0 = blockIdx.x * 128;
    const int lane = t & 31, wid = t >> 5;
    const int grp = lane >> 2, tq = lane & 3;
    const int wm = (wid & 1) * 64, wn = (wid >> 1) * 32;
    const int l15 = lane & 15, lhi = (lane >> 4) * 8;
    const __half* Ab = A + (size_t)m0 * K;
    const __half* Bb = B + (size_t)n0 * K;

    int cr[2], cc[2];
#pragma unroll
    for (int i = 0; i < 2; i++) {
        int idx = t + 256 * i;       // 0..511
        cr[i] = idx >> 2;            // 0..127
        cc[i] = (idx & 3) * 8;       // 0,8,16,24 halfs
    }

    float acc[4][4][4] = {};
    const int NKT = K >> 5;

    // prologue: stage 0 into buffer 0
#pragma unroll
    for (int i = 0; i < 2; i++) {
        cpa16(&sA[0][cr[i] * 40 + cc[i]], Ab + (size_t)cr[i] * K + cc[i]);
        cpa16(&sB[0][cr[i] * 40 + cc[i]], Bb + (size_t)cr[i] * K + cc[i]);
    }
    cp_commit();

    for (int kt = 0; kt < NKT; kt++) {
        int s = kt & 1;
        if (kt + 1 < NKT) {
            int kn = (kt + 1) * 32;
#pragma unroll
            for (int i = 0; i < 2; i++) {
                cpa16(&sA[s ^ 1][cr[i] * 40 + cc[i]], Ab + (size_t)cr[i] * K + kn + cc[i]);
                cpa16(&sB[s ^ 1][cr[i] * 40 + cc[i]], Bb + (size_t)cr[i] * K + kn + cc[i]);
            }
        }
        cp_commit();          // committed every iter (possibly empty) -> uniform accounting
        cp_wait1();           // retires stage kt (2 groups pending before this)
        __syncthreads();

        const __half* as = sA[s];
        const __half* bs = sB[s];
#pragma unroll
        for (int ks = 0; ks < 2; ks++) {
            unsigned af[4][4], bf[2][4];
#pragma unroll
            for (int mi = 0; mi < 4; mi++)
                ldsm4(af[mi], &as[(wm + mi * 16 + l15) * 40 + ks * 16 + lhi]);
#pragma unroll
            for (int nc = 0; nc < 2; nc++)
                ldsm4(bf[nc], &bs[(wn + nc * 16 + l15) * 40 + ks * 16 + lhi]);
#pragma unroll
            for (int mi = 0; mi < 4; mi++)
#pragma unroll
                for (int ni = 0; ni < 4; ni++) {
                    int nc = ni >> 1, w = ni & 1;
                    mma16(acc[mi][ni], af[mi], bf[nc][w], bf[nc][w + 2]);
                }
        }
        __syncthreads();      // all warps done reading buf s before next iter's cp.async hits s^1... and buf s is re-targeted at kt+2
    }

#pragma unroll
    for (int mi = 0; mi < 4; mi++)
#pragma unroll
        for (int ni = 0; ni < 4; ni++) {
            int col = n0 + wn + ni * 8 + 2 * tq;
            float b0 = 0.f, b1 = 0.f;
            if (HASBIAS) { b0 = __ldg(bias + col); b1 = __ldg(bias + col + 1); }
#pragma unroll
            for (int hh = 0; hh < 2; hh++) {
                int row = m0 + wm + mi * 16 + grp + hh * 8;
                float ox = acc[mi][ni][hh * 2 + 0] + b0;
                float oy = acc[mi][ni][hh * 2 + 1] + b1;
                if (RELU) { ox = fmaxf(ox, 0.f); oy = fmaxf(oy, 0.f); }
                if (OUTF16) {
                    unsigned hv = f2h2(ox, oy);
                    *(unsigned*)(Ch + (size_t)row * N + col) = hv;
                } else {
                    float2 o = {ox, oy};
                    *(float2*)(C + (size_t)row * N + col) = o;
                }
            }
        }
}

// ---------------- BDr = (q + r_r_bias) . rk^T  (fp16 mma -> fp16 out) -------
// Tiles with i0 + u0 < 385 are never read by flash (u >= 511 - i) -> skip.
__global__ __launch_bounds__(256) void qk_f16(
    const __half* __restrict__ qbase, const __half* __restrict__ rkh,
    const float* __restrict__ bias, __half* __restrict__ out) {
    int bh = blockIdx.z;
    int b = bh >> 4, h = bh & 15;
    int i0 = blockIdx.y * 64, j0 = blockIdx.x * 64;
    if (i0 + j0 < 385) return;   // fully-masked BDr tile: never read
    __shared__ __align__(16) __half Qs[64 * 72];
    __shared__ __align__(16) __half Ks[64 * 72];
    int t = threadIdx.x;
    const __half* qp = qbase + b * 3072 + h * 64;
    const __half* rkp = rkh + h * 64;   // per-head slice of rk (klen, H, dh)
    const float* bi = bias + h * 64;

#pragma unroll
    for (int i = 0; i < 2; i++) {
        int idx = t + 256 * i;       // 0..511
        int r = idx >> 3;            // 0..63
        int c = (idx & 7) * 8;       // 0..56  (c+8 <= 64 <= 72 stride: in-bounds)
        uint4 qv = *(const uint4*)(qp + (size_t)(i0 + r) * 24576 + c);
        const __half* qh = (const __half*)&qv;
        float4 b0 = *(const float4*)(bi + c);
        float4 b1 = *(const float4*)(bi + c + 4);
        uint4 o = make_uint4(
            f2h2(__half2float(qh[0]) + b0.x, __half2float(qh[1]) + b0.y),
            f2h2(__half2float(qh[2]) + b0.z, __half2float(qh[3]) + b0.w),
            f2h2(__half2float(qh[4]) + b1.x, __half2float(qh[5]) + b1.y),
            f2h2(__half2float(qh[6]) + b1.z, __half2float(qh[7]) + b1.w));
        *(uint4*)&Qs[r * 72 + c] = o;
        *(uint4*)&Ks[r * 72 + c] = *(const uint4*)(rkp + (size_t)(j0 + r) * DMODEL + c);
    }
    __syncthreads();

    int lane = t & 31, wid = t >> 5;
    int grp = lane >> 2, tq = lane & 3;
    int l15 = lane & 15, lhi = (lane >> 4) * 8;
    int wm = (wid & 1) * 32, wn = (wid >> 1) * 16;
    float acc[2][2][4] = {};

#pragma unroll
    for (int ks = 0; ks < 4; ks++) {
        unsigned af[2][4], bf[4];
#pragma unroll
        for (int mi = 0; mi < 2; mi++)
            ldsm4(af[mi], &Qs[(wm + mi * 16 + l15) * 72 + ks * 16 + lhi]);
        ldsm4(bf, &Ks[(wn + l15) * 72 + ks * 16 + lhi]);
#pragma unroll
        for (int mi = 0; mi < 2; mi++)
#pragma unroll
            for (int ni = 0; ni < 2; ni++)
                mma16(acc[mi][ni], af[mi], bf[ni], bf[ni + 2]);
    }

#pragma unroll
    for (int mi = 0; mi < 2; mi++)
#pragma unroll
        for (int ni = 0; ni < 2; ni++)
#pragma unroll
            for (int hh = 0; hh < 2; hh++) {
                int row = i0 + wm + mi * 16 + grp + hh * 8;
                int col = j0 + wn + ni * 8 + 2 * tq;
                unsigned hv = f2h2(acc[mi][ni][hh * 2], acc[mi][ni][hh * 2 + 1]);
                *(unsigned*)(out + ((size_t)bh * 512 + row) * 1024 + col) = hv;
            }
}

// ---------------- flash attention (fp16 + ldmatrix), 128 q-rows/block --------
// Block: 256 threads (8 warps), each warp owns 16 query rows.
__global__ __launch_bounds__(256) void flash_attn(
    const __half* __restrict__ qbase, const __half* __restrict__ kbase,
    const __half* __restrict__ vbase, const __half* __restrict__ BDr,
    const float* __restrict__ rwb, __half* __restrict__ outh) {
    __shared__ __align__(16) __half sQ[128 * 72];
    __shared__ __align__(16) __half sK[32 * 72];
    __shared__ __align__(16) __half sV[32 * 72];
    __shared__ __align__(16) __half sP[128 * 40];

    const int i0 = blockIdx.x * 128;
    const int bh = blockIdx.y;
    const int b = bh >> 4, h = bh & 15;
    const int t = threadIdx.x;
    const int lane = t & 31;
    const int wid = t >> 5;              // 0..7
    const int grp = lane >> 2, tq = lane & 3;
    const int l15 = lane & 15, lhi = (lane >> 4) * 8;
    const int wm = wid * 16;             // 0..112

    const __half* qp = qbase + b * 3072 + h * 64;
    const __half* kp = kbase + b * 3072 + h * 64;
    const __half* vp = vbase + b * 3072 + h * 64;
    const __half* bdp = BDr + (size_t)bh * QLEN * KLEN;

    // load Q + r_w_bias (128 rows x 64 halfs = 1024 uint4, 4 per thread)
#pragma unroll
    for (int i = 0; i < 4; i++) {
        int idx = t + 256 * i;
        int r = idx >> 3;            // 0..127
        int c = (idx & 7) * 8;       // 0..56
        uint4 qv = *(const uint4*)(qp + (size_t)(i0 + r) * 24576 + c);
        const __half* qh = (const __half*)&qv;
        float4 b0 = *(const float4*)(rwb + h * 64 + c);
        float4 b1 = *(const float4*)(rwb + h * 64 + c + 4);
        uint4 o = make_uint4(
            f2h2(__half2float(qh[0]) + b0.x, __half2float(qh[1]) + b0.y),
            f2h2(__half2float(qh[2]) + b0.z, __half2float(qh[3]) + b0.w),
            f2h2(__half2float(qh[4]) + b1.x, __half2float(qh[5]) + b1.y),
            f2h2(__half2float(qh[6]) + b1.z, __half2float(qh[7]) + b1.w));
        *(uint4*)&sQ[r * 72 + c] = o;
    }

    const int r0g = i0 + wm + grp;
    const int r1g = r0g + 8;
    float m0 = -3e38f, m1 = -3e38f, l0 = 0.f, l1 = 0.f;
    float oacc[8][4] = {};

    const int njt = (i0 + 640) >> 5;     // rows up to i0+127 attend j <= i+512
    for (int jt = 0; jt < njt; jt++) {
        const int j0 = jt * 32;
        __syncthreads();  // prior readers of sK/sV done (covers sQ on iter 0)
        // load K, V (32 rows x 64 halfs = 256 uint4 each, 1 per thread each)
        {
            int r = t >> 3;          // 0..31
            int c = (t & 7) * 8;     // 0..56
            *(uint4*)&sK[r * 72 + c] = *(const uint4*)(kp + (size_t)(j0 + r) * 24576 + c);
            *(uint4*)&sV[r * 72 + c] = *(const uint4*)(vp + (size_t)(j0 + r) * 24576 + c);
        }
        __syncthreads();

        // AC = Qw . K^T  (warp: 16 rows x 32 cols, K=64 -> 4 ksteps)
        float sacc[4][4] = {};
#pragma unroll
        for (int ks = 0; ks < 4; ks++) {
            unsigned a[4], bf0[4], bf1[4];
            ldsm4(a, &sQ[(wm + l15) * 72 + ks * 16 + lhi]);
            ldsm4(bf0, &sK[l15 * 72 + ks * 16 + lhi]);
            ldsm4(bf1, &sK[(16 + l15) * 72 + ks * 16 + lhi]);
            mma16(sacc[0], a, bf0[0], bf0[2]);
            mma16(sacc[1], a, bf0[1], bf0[3]);
            mma16(sacc[2], a, bf1[0], bf1[2]);
            mma16(sacc[3], a, bf1[1], bf1[3]);
        }

        // gather shifted BDr (fp16), scale, mask
        float sv[4][4];
#pragma unroll
        for (int ni = 0; ni < 4; ni++)
#pragma unroll
            for (int v = 0; v < 4; v++) {
                int jg = j0 + ni * 8 + 2 * tq + (v & 1);
                int ig = (v < 2) ? r0g : r1g;
                float x = -3e38f;
                if (jg <= ig + 512) {
                    float bd = __half2float(__ldg(bdp + (size_t)ig * KLEN + (jg + 511 - ig)));
                    x = (sacc[ni][v] + bd) * 0.125f;
                }
                sv[ni][v] = x;
            }

        // warp-local online softmax
        float rm0 = -3e38f, rm1 = -3e38f;
#pragma unroll
        for (int ni = 0; ni < 4; ni++) {
            rm0 = fmaxf(rm0, fmaxf(sv[ni][0], sv[ni][1]));
            rm1 = fmaxf(rm1, fmaxf(sv[ni][2], sv[ni][3]));
        }
        rm0 = fmaxf(rm0, __shfl_xor_sync(0xffffffff, rm0, 1));
        rm0 = fmaxf(rm0, __shfl_xor_sync(0xffffffff, rm0, 2));
        rm1 = fmaxf(rm1, __shfl_xor_sync(0xffffffff, rm1, 1));
        rm1 = fmaxf(rm1, __shfl_xor_sync(0xffffffff, rm1, 2));
        float mn0 = fmaxf(m0, rm0), mn1 = fmaxf(m1, rm1);
        float c0 = exp2f((m0 - mn0) * 1.44269504f);
        float c1 = exp2f((m1 - mn1) * 1.44269504f);
        float rs0 = 0.f, rs1 = 0.f;
#pragma unroll
        for (int ni = 0; ni < 4; ni++) {
            sv[ni][0] = exp2f((sv[ni][0] - mn0) * 1.44269504f);
            sv[ni][1] = exp2f((sv[ni][1] - mn0) * 1.44269504f);
            sv[ni][2] = exp2f((sv[ni][2] - mn1) * 1.44269504f);
            sv[ni][3] = exp2f((sv[ni][3] - mn1) * 1.44269504f);
            rs0 += sv[ni][0] + sv[ni][1];
            rs1 += sv[ni][2] + sv[ni][3];
        }
        rs0 += __shfl_xor_sync(0xffffffff, rs0, 1);
        rs0 += __shfl_xor_sync(0xffffffff, rs0, 2);
        rs1 += __shfl_xor_sync(0xffffffff, rs1, 1);
        rs1 += __shfl_xor_sync(0xffffffff, rs1, 2);
        l0 = l0 * c0 + rs0;
        l1 = l1 * c1 + rs1;
        m0 = mn0; m1 = mn1;
#pragma unroll
        for (int ni = 0; ni < 8; ni++) {
            oacc[ni][0] *= c0; oacc[ni][1] *= c0;
            oacc[ni][2] *= c1; oacc[ni][3] *= c1;
        }

        // write P (fp16) into sP (warp-private rows; no block barrier needed)
#pragma unroll
        for (int ni = 0; ni < 4; ni++) {
            int col = ni * 8 + 2 * tq;
            *(unsigned*)&sP[(wm + grp) * 40 + col] = f2h2(sv[ni][0], sv[ni][1]);
            *(unsigned*)&sP[(wm + grp + 8) * 40 + col] = f2h2(sv[ni][2], sv[ni][3]);
        }
        __syncwarp();

        // O += P . V  (K=32 -> 2 ksteps; V[j][d] loaded via ldmatrix.trans)
#pragma unroll
        for (int ks = 0; ks < 2; ks++) {
            unsigned a[4];
            ldsm4(a, &sP[(wm + l15) * 40 + ks * 16 + lhi]);
#pragma unroll
            for (int dg = 0; dg < 4; dg++) {
                unsigned bt[4];
                ldsm4t(bt, &sV[(ks * 16 + l15) * 72 + dg * 16 + lhi]);
                mma16(oacc[dg * 2 + 0], a, bt[0], bt[1]);
                mma16(oacc[dg * 2 + 1], a, bt[2], bt[3]);
            }
        }
    }

    // epilogue: normalize and store attn_vec (fp16)
    float inv0 = 1.f / l0, inv1 = 1.f / l1;
#pragma unroll
    for (int ni = 0; ni < 8; ni++) {
        int d = ni * 8 + 2 * tq;
        unsigned h0 = f2h2(oacc[ni][0] * inv0, oacc[ni][1] * inv0);
        unsigned h1v = f2h2(oacc[ni][2] * inv1, oacc[ni][3] * inv1);
        *(unsigned*)(outh + ((size_t)r0g * 8 + b) * 1024 + h * 64 + d) = h0;
        *(unsigned*)(outh + ((size_t)r1g * 8 + b) * 1024 + h * 64 + d) = h1v;
    }
}

// ---------------- residual + layernorm (fp32 out + fp16 copy) ----------------
__global__ __launch_bounds__(256) void resid_ln_kernel(
    const float* __restrict__ x, const float* __restrict__ y,
    const float* __restrict__ g, const float* __restrict__ bta,
    float* __restrict__ out, __half* __restrict__ outh) {
    __shared__ float red[256];
    int row = blockIdx.x, t = threadIdx.x;
    const float* xr = x + (size_t)row * 1024;
    const float* yr = y + (size_t)row * 1024;
    float v[4];
    float s = 0.f;
#pragma unroll
    for (int e = 0; e < 4; e++) {
        int c = t + 256 * e;
        v[e] = xr[c] + yr[c];
        s += v[e];
    }
    red[t] = s;
    __syncthreads();
    for (int w = 128; w > 0; w >>= 1) {
        if (t < w) red[t] += red[t + w];
        __syncthreads();
    }
    float mean = red[0] * (1.f / 1024.f);
    __syncthreads();
    float s2 = 0.f;
#pragma unroll
    for (int e = 0; e < 4; e++) {
        float d = v[e] - mean;
        s2 += d * d;
    }
    red[t] = s2;
    __syncthreads();
    for (int w = 128; w > 0; w >>= 1) {
        if (t < w) red[t] += red[t + w];
        __syncthreads();
    }
    float inv = rsqrtf(red[0] * (1.f / 1024.f) + 1e-5f);
#pragma unroll
    for (int e = 0; e < 4; e++) {
        int c = t + 256 * e;
        float o = (v[e] - mean) * inv * g[c] + bta[c];
        out[(size_t)row * 1024 + c] = o;
        outh[(size_t)row * 1024 + c] = __float2half(o);
    }
}

// ---------------- host orchestration ----------------
extern "C" void kernel_launch(void* const* d_in, const int* in_sizes, int n_in,
                              void* d_out, int out_size) {
    const int* inp = (const int*)d_in[0];
    const float* mems = (const float*)d_in[1];
    const float* emb_table = (const float*)d_in[2];
    const float* r_w_bias = (const float*)d_in[3];
    const float* r_r_bias = (const float*)d_in[4];
    const float* qkv_w = (const float*)d_in[5];
    const float* r_w = (const float*)d_in[6];
    const float* o_w = (const float*)d_in[7];
    const float* ln1_g = (const float*)d_in[8];
    const float* ln1_b = (const float*)d_in[9];
    const float* ff_w1 = (const float*)d_in[10];
    const float* ff_b1 = (const float*)d_in[11];
    const float* ff_w2 = (const float*)d_in[12];
    const float* ff_b2 = (const float*)d_in[13];
    const float* ln2_g = (const float*)d_in[14];
    const float* ln2_b = (const float*)d_in[15];

    void* p;
    cudaGetSymbolAddress(&p, g_core);    float* corep = (float*)p;
    cudaGetSymbolAddress(&p, g_attnout); float* aoutp = (float*)p;
    cudaGetSymbolAddress(&p, g_ff);      float* ffp = (float*)p;
    cudaGetSymbolAddress(&p, g_BDrh);    __half* bdrp = (__half*)p;
    cudaGetSymbolAddress(&p, g_headsh);  __half* headshp = (__half*)p;
    cudaGetSymbolAddress(&p, g_cath);    __half* cathp = (__half*)p;
    cudaGetSymbolAddress(&p, g_pemh);    __half* pemhp = (__half*)p;
    cudaGetSymbolAddress(&p, g_rkh);     __half* rkhp = (__half*)p;
    cudaGetSymbolAddress(&p, g_coreh);   __half* corehp = (__half*)p;
    cudaGetSymbolAddress(&p, g_avech);   __half* avechp = (__half*)p;
    cudaGetSymbolAddress(&p, g_h1h);     __half* h1hp = (__half*)p;
    cudaGetSymbolAddress(&p, g_qkvwh);   __half* qkvwhp = (__half*)p;
    cudaGetSymbolAddress(&p, g_rwh);     __half* rwhp = (__half*)p;
    cudaGetSymbolAddress(&p, g_owh);     __half* owhp = (__half*)p;
    cudaGetSymbolAddress(&p, g_w1h);     __half* w1hp = (__half*)p;
    cudaGetSymbolAddress(&p, g_w2h);     __half* w2hp = (__half*)p;

    const size_t CORE_BYTES = (size_t)QLEN * BSZ * DMODEL * sizeof(float);

    // weight conversions (once per launch)
    {
        int n;
        n = 4 * 3 * DMODEL * DMODEL / 4;
        w2h_kernel<<<n / 256, 256>>>(qkv_w, qkvwhp, n);
        n = 4 * DMODEL * DMODEL / 4;
        w2h_kernel<<<n / 256, 256>>>(r_w, rwhp, n);
        w2h_kernel<<<n / 256, 256>>>(o_w, owhp, n);
        n = 4 * DINNER * DMODEL / 4;
        w2h_kernel<<<n / 256, 256>>>(ff_w1, w1hp, n);
        w2h_kernel<<<n / 256, 256>>>(ff_w2, w2hp, n);
    }

    embed_kernel<<<QLEN * BSZ, 256>>>(inp, emb_table, corep);
    posemb_kernel<<<KLEN, 512>>>(pemhp);

    const __half* qh = headshp + (size_t)MLEN * BSZ * 3 * DMODEL;

    for (int l = 0; l < 4; l++) {
        // cat_h = fp16([mems[l]; core])
        cat_f16_kernel<<<KLEN * BSZ, 256>>>(
            mems + (size_t)l * MLEN * BSZ * DMODEL, corep, cathp);
        // heads = cat @ qkv_w[l]^T   (8192 x 3072 x 1024) fp16 out
        gemm_nt_h<false, false, true><<<dim3(24, 64), 256>>>(
            cathp, qkvwhp + (size_t)l * 3 * DMODEL * DMODEL, nullptr,
            nullptr, headshp, KLEN * BSZ, 3 * DMODEL, DMODEL);
        // rk = pos_emb @ r_w[l]^T    (1024 x 1024 x 1024) fp16 out
        gemm_nt_h<false, false, true><<<dim3(8, 8), 256>>>(
            pemhp, rwhp + (size_t)l * DMODEL * DMODEL, nullptr,
            nullptr, rkhp, KLEN, DMODEL, DMODEL);
        // BDr = (q + r_r_bias) . rk   (fp16 out, dead tiles skipped)
        qk_f16<<<dim3(16, 8, 128), 256>>>(qh, rkhp, r_r_bias, bdrp);
        // flash attention -> avec (fp16)
        flash_attn<<<dim3(4, 128), 256>>>(
            qh, headshp + DMODEL, headshp + 2 * DMODEL, bdrp, r_w_bias, avechp);
        // attn_out = attn_vec @ o_w[l]^T   (4096 x 1024 x 1024) fp32 out
        gemm_nt_h<false, false, false><<<dim3(8, 32), 256>>>(
            avechp, owhp + (size_t)l * DMODEL * DMODEL, nullptr,
            aoutp, nullptr, QLEN * BSZ, DMODEL, DMODEL);
        resid_ln_kernel<<<QLEN * BSZ, 256>>>(corep, aoutp, ln1_g + l * DMODEL,
                                             ln1_b + l * DMODEL, corep, corehp);
        // h1 = relu(core @ ff_w1^T + b1)   (4096 x 4096 x 1024) fp16 out
        gemm_nt_h<true, true, true><<<dim3(32, 32), 256>>>(
            corehp, w1hp + (size_t)l * DINNER * DMODEL, ff_b1 + l * DINNER,
            nullptr, h1hp, QLEN * BSZ, DINNER, DMODEL);
        // ff = h1 @ ff_w2^T + b2           (4096 x 1024 x 4096) fp32 out
        gemm_nt_h<false, true, false><<<dim3(8, 32), 256>>>(
            h1hp, w2hp + (size_t)l * DMODEL * DINNER, ff_b2 + l * DMODEL,
            ffp, nullptr, QLEN * BSZ, DMODEL, DINNER);
        resid_ln_kernel<<<QLEN * BSZ, 256>>>(corep, ffp, ln2_g + l * DMODEL,
                                             ln2_b + l * DMODEL, corep, corehp);
    }

    cudaMemcpyAsync(d_out, corep, CORE_BYTES, cudaMemcpyDeviceToDevice);
}